// round 1
// baseline (speedup 1.0000x reference)
#include <cuda_runtime.h>

// DVBundle: I[n,k] = sum_i w[n,i,k]*x[i,k];  dv=(I0-I1+I2-I3-v)*DT/TAU_V
// w_new = w + (r*actd(v)*dv) * (x*ALPHA - w*I[k]) / TAU_W
// r_new = act(v); v_new = v + dv
//
// Shapes: w [4096, 8192, 4] f32 (k contiguous -> float4 per (n,i)),
//         x [8192, 4] f32, v [4096], r [4096].
// Output layout: [v_new (N) | r_new (N) | w_new (N*NI*4)]

#define N_INPUTS  8192
#define THREADS   1024
#define VPT       (N_INPUTS / THREADS)   // float4s per thread = 8

__global__ __launch_bounds__(THREADS, 1)
void dvbundle_kernel(const float4* __restrict__ w,
                     const float4* __restrict__ x,
                     const float*  __restrict__ v,
                     const float*  __restrict__ r,
                     float*        __restrict__ v_out,
                     float*        __restrict__ r_out,
                     float4*       __restrict__ w_out)
{
    extern __shared__ float4 smem[];          // [N_INPUTS] x-cache + [32] reduce
    float4* xs  = smem;
    float4* red = smem + N_INPUTS;

    const int    n     = blockIdx.x;
    const int    tid   = threadIdx.x;
    const size_t wbase = (size_t)n * N_INPUTS;

    // ---- Pass 1: load w row into registers, cache x in smem, partial I ----
    float4 wv[VPT];
    float ax = 0.f, ay = 0.f, az = 0.f, aw = 0.f;
#pragma unroll
    for (int j = 0; j < VPT; ++j) {
        const int i = tid + j * THREADS;
        const float4 xv = x[i];
        const float4 wj = w[wbase + i];
        wv[j] = wj;
        xs[i] = xv;
        ax = fmaf(wj.x, xv.x, ax);
        ay = fmaf(wj.y, xv.y, ay);
        az = fmaf(wj.z, xv.z, az);
        aw = fmaf(wj.w, xv.w, aw);
    }

    // ---- Block reduction of (ax,ay,az,aw) over 1024 threads ----
#pragma unroll
    for (int o = 16; o > 0; o >>= 1) {
        ax += __shfl_xor_sync(0xffffffffu, ax, o);
        ay += __shfl_xor_sync(0xffffffffu, ay, o);
        az += __shfl_xor_sync(0xffffffffu, az, o);
        aw += __shfl_xor_sync(0xffffffffu, aw, o);
    }
    const int warp = tid >> 5;
    const int lane = tid & 31;
    if (lane == 0) red[warp] = make_float4(ax, ay, az, aw);
    __syncthreads();
    if (warp == 0) {
        float4 t4 = red[lane];                // 32 warps -> 32 lanes
        ax = t4.x; ay = t4.y; az = t4.z; aw = t4.w;
#pragma unroll
        for (int o = 16; o > 0; o >>= 1) {
            ax += __shfl_xor_sync(0xffffffffu, ax, o);
            ay += __shfl_xor_sync(0xffffffffu, ay, o);
            az += __shfl_xor_sync(0xffffffffu, az, o);
            aw += __shfl_xor_sync(0xffffffffu, aw, o);
        }
        if (lane == 0) red[0] = make_float4(ax, ay, az, aw);
    }
    __syncthreads();
    const float4 I = red[0];

    // ---- Scalar neuron update ----
    const float vn = v[n];
    const float rn = r[n];
    const float S  = I.x - I.y + I.z - I.w;
    const float dv = (S - vn) * 0.05f;                 // DT/TAU_V = 0.01/0.2
    const float th = tanhf(vn);
    const float actd = (vn > 0.f) ? (1.f - th * th) : 0.f;
    const float reg  = rn * actd * dv * 0.02f;         // / TAU_W (=50)

    if (tid == 0) {
        v_out[n] = vn + dv;
        r_out[n] = (vn > 0.f) ? th : 0.f;
    }

    // ---- Pass 2: w_new = w + reg*(0.5*x - w*I[k]), w from regs, x from smem ----
#pragma unroll
    for (int j = 0; j < VPT; ++j) {
        const int i = tid + j * THREADS;
        const float4 xv = xs[i];
        const float4 wj = wv[j];
        float4 o;
        o.x = fmaf(reg, fmaf(-wj.x, I.x, 0.5f * xv.x), wj.x);
        o.y = fmaf(reg, fmaf(-wj.y, I.y, 0.5f * xv.y), wj.y);
        o.z = fmaf(reg, fmaf(-wj.z, I.z, 0.5f * xv.z), wj.z);
        o.w = fmaf(reg, fmaf(-wj.w, I.w, 0.5f * xv.w), wj.w);
        w_out[wbase + i] = o;
    }
}

extern "C" void kernel_launch(void* const* d_in, const int* in_sizes, int n_in,
                              void* d_out, int out_size)
{
    const float4* w = (const float4*)d_in[0];
    const float4* x = (const float4*)d_in[1];
    const float*  v = (const float*)d_in[2];
    const float*  r = (const float*)d_in[3];

    const int N = in_sizes[2];                 // 4096 neurons

    float*  out   = (float*)d_out;
    float*  v_out = out;
    float*  r_out = out + N;
    float4* w_out = (float4*)(out + 2 * (size_t)N);

    const size_t smem_bytes = (N_INPUTS + 32) * sizeof(float4);  // 131584 B
    cudaFuncSetAttribute(dvbundle_kernel,
                         cudaFuncAttributeMaxDynamicSharedMemorySize,
                         (int)smem_bytes);

    dvbundle_kernel<<<N, THREADS, smem_bytes>>>(w, x, v, r, v_out, r_out, w_out);
}

// round 2
// speedup vs baseline: 1.0609x; 1.0609x over previous
#include <cuda_runtime.h>

// DVBundle persistent kernel.
// I[n,k] = sum_i w[n,i,k]*x[i,k];  dv=(I0-I1+I2-I3-v)*DT/TAU_V
// w_new = w + (r*actd(v)*dv) * (0.5*x - w*I[k]) / TAU_W
// r_new = act(v); v_new = v + dv
//
// w [4096, 8192, 4] f32 (k contiguous -> float4 per (n,i)), x [8192,4], v/r [4096].
// Output: [v_new (N) | r_new (N) | w_new (N*NI*4)]
//
// Grid = 148 persistent CTAs (one wave). Each CTA loops over neurons with
// stride gridDim.x, keeps the current w row in registers, caches x in smem
// once, and prefetches the NEXT neuron's w row during the pass-2 store loop
// so DRAM loads stay in flight across the reduction/barrier bubble.

#define N_INPUTS  8192
#define THREADS   1024
#define VPT       (N_INPUTS / THREADS)   // 8 float4 per thread
#define GRID_P    148

__global__ __launch_bounds__(THREADS, 1)
void dvbundle_persist(const float4* __restrict__ w,
                      const float4* __restrict__ x,
                      const float*  __restrict__ v,
                      const float*  __restrict__ r,
                      float*        __restrict__ v_out,
                      float*        __restrict__ r_out,
                      float4*       __restrict__ w_out,
                      int n_neurons)
{
    extern __shared__ float4 smem[];      // [0..8191] x cache, [8192..8224] reduce
    float4* xs  = smem;
    float4* red = smem + N_INPUTS;        // [0..31] warp partials, [32] broadcast

    const int tid    = threadIdx.x;
    const int warp   = tid >> 5;
    const int lane   = tid & 31;
    const int stride = gridDim.x;

    // ---- Prologue: cache x in smem; load first w row into registers ----
    int n = blockIdx.x;
    float4 wv[VPT];
#pragma unroll
    for (int j = 0; j < VPT; ++j) {
        const int i = tid + j * THREADS;
        xs[i] = x[i];
    }
    if (n < n_neurons) {
        const size_t wbase = (size_t)n * N_INPUTS;
#pragma unroll
        for (int j = 0; j < VPT; ++j)
            wv[j] = w[wbase + tid + j * THREADS];
    }
    __syncthreads();

    for (; n < n_neurons; n += stride) {
        // ---- Pass 1: partial I from registers (loads issued last iteration) ----
        float ax = 0.f, ay = 0.f, az = 0.f, aw = 0.f;
#pragma unroll
        for (int j = 0; j < VPT; ++j) {
            const int i = tid + j * THREADS;
            const float4 xv = xs[i];
            ax = fmaf(wv[j].x, xv.x, ax);
            ay = fmaf(wv[j].y, xv.y, ay);
            az = fmaf(wv[j].z, xv.z, az);
            aw = fmaf(wv[j].w, xv.w, aw);
        }

        // ---- Block reduction over 1024 threads ----
#pragma unroll
        for (int o = 16; o > 0; o >>= 1) {
            ax += __shfl_xor_sync(0xffffffffu, ax, o);
            ay += __shfl_xor_sync(0xffffffffu, ay, o);
            az += __shfl_xor_sync(0xffffffffu, az, o);
            aw += __shfl_xor_sync(0xffffffffu, aw, o);
        }
        if (lane == 0) red[warp] = make_float4(ax, ay, az, aw);
        __syncthreads();
        if (warp == 0) {
            float4 t4 = red[lane];
            ax = t4.x; ay = t4.y; az = t4.z; aw = t4.w;
#pragma unroll
            for (int o = 16; o > 0; o >>= 1) {
                ax += __shfl_xor_sync(0xffffffffu, ax, o);
                ay += __shfl_xor_sync(0xffffffffu, ay, o);
                az += __shfl_xor_sync(0xffffffffu, az, o);
                aw += __shfl_xor_sync(0xffffffffu, aw, o);
            }
            if (lane == 0) red[32] = make_float4(ax, ay, az, aw);
        }
        __syncthreads();
        const float4 I = red[32];

        // ---- Scalar neuron update ----
        const float vn   = v[n];
        const float rn   = r[n];
        const float S    = I.x - I.y + I.z - I.w;
        const float dv   = (S - vn) * 0.05f;            // DT/TAU_V
        const float th   = tanhf(vn);
        const float actd = (vn > 0.f) ? (1.f - th * th) : 0.f;
        const float reg  = rn * actd * dv * 0.02f;      // / TAU_W

        if (tid == 0) {
            v_out[n] = vn + dv;
            r_out[n] = (vn > 0.f) ? th : 0.f;
        }

        // ---- Pass 2: write w_new; prefetch next neuron's w row ----
        const size_t wbase  = (size_t)n * N_INPUTS;
        const int    n2     = n + stride;
        const bool   nx     = (n2 < n_neurons);
        const size_t wbase2 = (size_t)n2 * N_INPUTS;
#pragma unroll
        for (int j = 0; j < VPT; ++j) {
            const int i = tid + j * THREADS;
            const float4 xv = xs[i];
            const float4 wj = wv[j];
            float4 o;
            o.x = fmaf(reg, fmaf(-wj.x, I.x, 0.5f * xv.x), wj.x);
            o.y = fmaf(reg, fmaf(-wj.y, I.y, 0.5f * xv.y), wj.y);
            o.z = fmaf(reg, fmaf(-wj.z, I.z, 0.5f * xv.z), wj.z);
            o.w = fmaf(reg, fmaf(-wj.w, I.w, 0.5f * xv.w), wj.w);
            w_out[wbase + i] = o;
            if (nx) wv[j] = w[wbase2 + i];   // prefetch next row into same regs
        }
    }
}

extern "C" void kernel_launch(void* const* d_in, const int* in_sizes, int n_in,
                              void* d_out, int out_size)
{
    const float4* w = (const float4*)d_in[0];
    const float4* x = (const float4*)d_in[1];
    const float*  v = (const float*)d_in[2];
    const float*  r = (const float*)d_in[3];

    const int N = in_sizes[2];                 // 4096 neurons

    float*  out   = (float*)d_out;
    float*  v_out = out;
    float*  r_out = out + N;
    float4* w_out = (float4*)(out + 2 * (size_t)N);

    const size_t smem_bytes = (N_INPUTS + 40) * sizeof(float4);  // ~128.6 KB
    cudaFuncSetAttribute(dvbundle_persist,
                         cudaFuncAttributeMaxDynamicSharedMemorySize,
                         (int)smem_bytes);

    dvbundle_persist<<<GRID_P, THREADS, smem_bytes>>>(w, x, v, r,
                                                      v_out, r_out, w_out, N);
}